// round 1
// baseline (speedup 1.0000x reference)
#include <cuda_runtime.h>
#include <math.h>

#define BB 4
#define NN 1024
#define CC 768
#define HH 12
#define HD 64
#define QKV3 (3*CC)          // 2304
#define MROWS (2*BB*NN)      // 8192 (both streams)
#define PERSB (HH*NN*HD)     // 786432 floats per (stream,b)

// -------- scratch (device globals; no allocation) --------
__device__ float g_qkv[2*BB*NN*QKV3];        // [s][b][n][2304]
__device__ float g_q  [2*BB*HH*NN*HD];       // [s][b][h][n][d]
__device__ float g_k  [2*BB*HH*NN*HD];
__device__ float g_v  [2*BB*HH*NN*HD];
__device__ float g_ctx[2*BB*HH*NN*HD];       // [p][b][h][n][d], p=0:context_b, p=1:context_a

// =====================================================================
// Kernel 1: QKV GEMM.  Y[m, j] = X[m, :] . Wqkv[j, :]
// m in [0,8192): stream = m>>12.  Tiled 64x64x16, 256 thr, 4x4/thread.
// =====================================================================
__global__ void qkv_gemm(const float* __restrict__ before,
                         const float* __restrict__ after,
                         const float* __restrict__ Wqkv) {
    __shared__ float As[16*64];
    __shared__ float Bs[16*64];
    const int tid = threadIdx.x;
    const int ty = tid >> 4, tx = tid & 15;
    const int lrow = tid >> 2;          // 0..63
    const int kq = (tid & 3) * 4;       // 0,4,8,12

    const int mt = blockIdx.y, nt = blockIdx.x;
    const int gm = mt*64 + lrow;
    const int stream = gm >> 12;
    const int r = gm & 4095;
    const float* X = (stream ? after : before) + (size_t)r*CC;
    const float* W = Wqkv + (size_t)(nt*64 + lrow)*CC;

    float acc[4][4] = {};
    for (int k0 = 0; k0 < CC; k0 += 16) {
        float4 a4 = *(const float4*)(X + k0 + kq);
        float4 b4 = *(const float4*)(W + k0 + kq);
        As[(kq+0)*64 + lrow] = a4.x; As[(kq+1)*64 + lrow] = a4.y;
        As[(kq+2)*64 + lrow] = a4.z; As[(kq+3)*64 + lrow] = a4.w;
        Bs[(kq+0)*64 + lrow] = b4.x; Bs[(kq+1)*64 + lrow] = b4.y;
        Bs[(kq+2)*64 + lrow] = b4.z; Bs[(kq+3)*64 + lrow] = b4.w;
        __syncthreads();
        #pragma unroll
        for (int kk = 0; kk < 16; kk++) {
            float ra[4], rb[4];
            #pragma unroll
            for (int i = 0; i < 4; i++) ra[i] = As[kk*64 + ty*4 + i];
            #pragma unroll
            for (int j = 0; j < 4; j++) rb[j] = Bs[kk*64 + tx*4 + j];
            #pragma unroll
            for (int i = 0; i < 4; i++)
                #pragma unroll
                for (int j = 0; j < 4; j++)
                    acc[i][j] = fmaf(ra[i], rb[j], acc[i][j]);
        }
        __syncthreads();
    }
    #pragma unroll
    for (int i = 0; i < 4; i++) {
        const size_t row = (size_t)(mt*64 + ty*4 + i);
        #pragma unroll
        for (int j = 0; j < 4; j++)
            g_qkv[row*QKV3 + nt*64 + tx*4 + j] = acc[i][j];
    }
}

// =====================================================================
// Kernel 2: LayerNorm over head_dim=64; scatter to q/k/v [s][b][h][n][d]
// One warp per vector; 8 warps per block.
// =====================================================================
__global__ void ln_head(const float* __restrict__ ln_g,
                        const float* __restrict__ ln_b) {
    const int warp = threadIdx.x >> 5;
    const int lane = threadIdx.x & 31;
    const int v = blockIdx.x*8 + warp;   // [s][b][n][t][h]
    const int h = v % 12;
    const int t = (v/12) % 3;
    const int n = (v/36) % NN;
    const int b = (v/(36*NN)) % BB;
    const int s = v/(36*NN*BB);

    const float* src = g_qkv + (((size_t)(s*BB+b)*NN + n)*QKV3) + t*CC + h*HD;
    float x0 = src[lane], x1 = src[lane+32];
    float sum = x0 + x1, sq = x0*x0 + x1*x1;
    #pragma unroll
    for (int o = 16; o > 0; o >>= 1) {
        sum += __shfl_xor_sync(0xffffffffu, sum, o);
        sq  += __shfl_xor_sync(0xffffffffu, sq,  o);
    }
    const float mean = sum * (1.f/64.f);
    const float var  = sq  * (1.f/64.f) - mean*mean;
    const float rstd = rsqrtf(var + 1e-5f);

    float* dst = (t == 0 ? g_q : (t == 1 ? g_k : g_v))
               + ((((size_t)(s*BB+b)*HH + h)*NN + n)*HD);
    dst[lane]    = (x0 - mean)*rstd*ln_g[lane]    + ln_b[lane];
    dst[lane+32] = (x1 - mean)*rstd*ln_g[lane+32] + ln_b[lane+32];
}

// =====================================================================
// Kernel 3: attention, flash-style. Block = (p,b,h,qtile). 256 threads.
// p=0: context_b = attn(q_after, k_before, v_before)
// p=1: context_a = attn(q_before, k_after, v_after)
// =====================================================================
__global__ void attn_kernel() {
    extern __shared__ float sm[];
    float* Qs = sm;               // [64][65]
    float* Ks = Qs + 64*65;
    float* Vs = Ks + 64*65;
    float* Ps = Vs + 64*65;
    float* corr_s = Ps + 64*65;   // [64]
    float* l_s = corr_s + 64;     // [64]

    const int bx = blockIdx.x;
    const int qt = bx & 15;
    const int h  = (bx >> 4) % 12;
    const int b  = (bx / (16*12)) & 3;
    const int p  = bx / (16*12*4);
    const int qs = 1 - p, kvs = p;

    const float* qptr = g_q + (((size_t)(qs*BB+b)*HH + h)*NN + qt*64)*HD;
    const float* kptr = g_k + (((size_t)(kvs*BB+b)*HH + h)*NN)*HD;
    const float* vptr = g_v + (((size_t)(kvs*BB+b)*HH + h)*NN)*HD;

    const int tid = threadIdx.x;
    const int ty = tid >> 4, tx = tid & 15;
    const int srow = tid >> 2, st = tid & 3;

    // load Q tile (64x64) into padded smem
    #pragma unroll
    for (int it = 0; it < 4; it++) {
        int lin = tid + it*256;
        int row = lin >> 4, c4 = (lin & 15)*4;
        float4 q4 = *(const float4*)(qptr + row*64 + c4);
        Qs[row*65 + c4+0] = q4.x; Qs[row*65 + c4+1] = q4.y;
        Qs[row*65 + c4+2] = q4.z; Qs[row*65 + c4+3] = q4.w;
    }

    float O[4][4] = {};
    float m_run = -1e30f, l_run = 0.f;

    for (int kc = 0; kc < 16; kc++) {
        __syncthreads();   // protect prev-iter Ks/Vs/Ps reads (also fences Q load)
        const float* kp = kptr + kc*64*64;
        const float* vp = vptr + kc*64*64;
        #pragma unroll
        for (int it = 0; it < 4; it++) {
            int lin = tid + it*256;
            int row = lin >> 4, c4 = (lin & 15)*4;
            float4 k4 = *(const float4*)(kp + row*64 + c4);
            Ks[row*65 + c4+0] = k4.x; Ks[row*65 + c4+1] = k4.y;
            Ks[row*65 + c4+2] = k4.z; Ks[row*65 + c4+3] = k4.w;
            float4 v4 = *(const float4*)(vp + row*64 + c4);
            Vs[row*65 + c4+0] = v4.x; Vs[row*65 + c4+1] = v4.y;
            Vs[row*65 + c4+2] = v4.z; Vs[row*65 + c4+3] = v4.w;
        }
        __syncthreads();

        // S = scale * Q K^T  (4x4 per thread)
        float s[4][4] = {};
        #pragma unroll
        for (int kk = 0; kk < 64; kk++) {
            float ra[4], rb[4];
            #pragma unroll
            for (int i = 0; i < 4; i++) ra[i] = Qs[(ty*4+i)*65 + kk];
            #pragma unroll
            for (int j = 0; j < 4; j++) rb[j] = Ks[(tx*4+j)*65 + kk];
            #pragma unroll
            for (int i = 0; i < 4; i++)
                #pragma unroll
                for (int j = 0; j < 4; j++)
                    s[i][j] = fmaf(ra[i], rb[j], s[i][j]);
        }
        #pragma unroll
        for (int i = 0; i < 4; i++)
            #pragma unroll
            for (int j = 0; j < 4; j++)
                Ps[(ty*4+i)*65 + tx*4+j] = s[i][j]*0.125f;
        __syncthreads();

        // online softmax: 4 threads per row, 16 cols each
        float* base = Ps + srow*65 + st*16;
        float lmax = -1e30f;
        #pragma unroll
        for (int jj = 0; jj < 16; jj++) lmax = fmaxf(lmax, base[jj]);
        lmax = fmaxf(lmax, __shfl_xor_sync(0xffffffffu, lmax, 1));
        lmax = fmaxf(lmax, __shfl_xor_sync(0xffffffffu, lmax, 2));
        const float mnew = fmaxf(m_run, lmax);
        const float corr = __expf(m_run - mnew);
        float lsum = 0.f;
        #pragma unroll
        for (int jj = 0; jj < 16; jj++) {
            float e = __expf(base[jj] - mnew);
            base[jj] = e;
            lsum += e;
        }
        lsum += __shfl_xor_sync(0xffffffffu, lsum, 1);
        lsum += __shfl_xor_sync(0xffffffffu, lsum, 2);
        l_run = l_run*corr + lsum;
        m_run = mnew;
        if (st == 0) corr_s[srow] = corr;
        __syncthreads();

        // rescale O, then O += P @ V
        #pragma unroll
        for (int i = 0; i < 4; i++) {
            const float c_ = corr_s[ty*4+i];
            #pragma unroll
            for (int j = 0; j < 4; j++) O[i][j] *= c_;
        }
        #pragma unroll
        for (int kk = 0; kk < 64; kk++) {
            float rp[4], rv[4];
            #pragma unroll
            for (int i = 0; i < 4; i++) rp[i] = Ps[(ty*4+i)*65 + kk];
            #pragma unroll
            for (int j = 0; j < 4; j++) rv[j] = Vs[kk*65 + tx*4+j];
            #pragma unroll
            for (int i = 0; i < 4; i++)
                #pragma unroll
                for (int j = 0; j < 4; j++)
                    O[i][j] = fmaf(rp[i], rv[j], O[i][j]);
        }
    }
    if (st == 0) l_s[srow] = l_run;
    __syncthreads();

    float* op = g_ctx + (((size_t)(p*BB+b)*HH + h)*NN + qt*64)*HD;
    #pragma unroll
    for (int i = 0; i < 4; i++) {
        const float inv = 1.f / l_s[ty*4+i];
        #pragma unroll
        for (int j = 0; j < 4; j++)
            op[(ty*4+i)*64 + tx*4+j] = O[i][j]*inv;
    }
}

// =====================================================================
// Kernel 4: projection GEMM + bias + flat-q residual, straight to d_out.
// out[p][b][n][c] = sum_k ctx[p][b][h(k)][n][d(k)] * Wp[c][k] + bias[c]
//                 + q_flat[qs(p)][b][n*768 + c]
// =====================================================================
__global__ void proj_gemm(const float* __restrict__ Wp,
                          const float* __restrict__ bias,
                          float* __restrict__ out) {
    __shared__ float As[16*64];
    __shared__ float Bs[16*64];
    const int tid = threadIdx.x;
    const int ty = tid >> 4, tx = tid & 15;
    const int lrow = tid >> 2;
    const int kq = (tid & 3) * 4;

    const int mt = blockIdx.y, nt = blockIdx.x;
    const int gm = mt*64 + lrow;
    const int p = gm >> 12;
    const int r = gm & 4095;
    const int b = r >> 10;
    const int n = r & 1023;

    const float* actx = g_ctx + (size_t)(p*BB+b)*PERSB;   // [h][n][d]
    const float* W = Wp + (size_t)(nt*64 + lrow)*CC;

    float acc[4][4] = {};
    for (int k0 = 0; k0 < CC; k0 += 16) {
        const int k = k0 + kq;
        const int h = k >> 6, d = k & 63;
        float4 a4 = *(const float4*)(actx + ((size_t)h*NN + n)*HD + d);
        float4 b4 = *(const float4*)(W + k);
        As[(kq+0)*64 + lrow] = a4.x; As[(kq+1)*64 + lrow] = a4.y;
        As[(kq+2)*64 + lrow] = a4.z; As[(kq+3)*64 + lrow] = a4.w;
        Bs[(kq+0)*64 + lrow] = b4.x; Bs[(kq+1)*64 + lrow] = b4.y;
        Bs[(kq+2)*64 + lrow] = b4.z; Bs[(kq+3)*64 + lrow] = b4.w;
        __syncthreads();
        #pragma unroll
        for (int kk = 0; kk < 16; kk++) {
            float ra[4], rb[4];
            #pragma unroll
            for (int i = 0; i < 4; i++) ra[i] = As[kk*64 + ty*4 + i];
            #pragma unroll
            for (int j = 0; j < 4; j++) rb[j] = Bs[kk*64 + tx*4 + j];
            #pragma unroll
            for (int i = 0; i < 4; i++)
                #pragma unroll
                for (int j = 0; j < 4; j++)
                    acc[i][j] = fmaf(ra[i], rb[j], acc[i][j]);
        }
        __syncthreads();
    }

    #pragma unroll
    for (int i = 0; i < 4; i++) {
        const int grow = mt*64 + ty*4 + i;
        const int pp = grow >> 12;
        const int rr = grow & 4095;
        const int bb2 = rr >> 10;
        const int nn2 = rr & 1023;
        const int qs = 1 - pp;
        const float* qres = g_q + (size_t)(qs*BB+bb2)*PERSB + (size_t)nn2*CC;
        #pragma unroll
        for (int j = 0; j < 4; j++) {
            const int c = nt*64 + tx*4 + j;
            out[(size_t)grow*CC + c] = acc[i][j] + bias[c] + qres[c];
        }
    }
}

// =====================================================================
extern "C" void kernel_launch(void* const* d_in, const int* in_sizes, int n_in,
                              void* d_out, int out_size) {
    const float* before = (const float*)d_in[0];
    const float* after  = (const float*)d_in[1];
    const float* W_qkv  = (const float*)d_in[2];
    const float* ln_g   = (const float*)d_in[3];
    const float* ln_b   = (const float*)d_in[4];
    const float* W_proj = (const float*)d_in[5];
    const float* b_proj = (const float*)d_in[6];
    float* out = (float*)d_out;

    // 1) QKV GEMM: grid (2304/64, 8192/64)
    {
        dim3 grid(QKV3/64, MROWS/64);
        qkv_gemm<<<grid, 256>>>(before, after, W_qkv);
    }
    // 2) LayerNorm: 2*B*N*3*H = 294912 vectors, 8 per block
    {
        ln_head<<<294912/8, 256>>>(ln_g, ln_b);
    }
    // 3) Attention: 2*4*12*16 = 1536 blocks, 67KB dyn smem
    {
        const int smem = (4*64*65 + 128) * (int)sizeof(float);
        cudaFuncSetAttribute(attn_kernel, cudaFuncAttributeMaxDynamicSharedMemorySize, smem);
        attn_kernel<<<1536, 256, smem>>>();
    }
    // 4) Projection GEMM: grid (768/64, 8192/64)
    {
        dim3 grid(CC/64, MROWS/64);
        proj_gemm<<<grid, 256>>>(W_proj, b_proj, out);
    }
}

// round 3
// speedup vs baseline: 2.7044x; 2.7044x over previous
#include <cuda_runtime.h>
#include <math.h>

#define BB 4
#define NN 1024
#define CC 768
#define HH 12
#define HD 64
#define QKV3 (3*CC)          // 2304
#define MROWS (2*BB*NN)      // 8192
#define PERSB (HH*NN*HD)     // 786432 floats per (stream,b)

// -------- scratch (device globals; no allocation) --------
__device__ float g_q  [2*BB*HH*NN*HD];   // [s][b][h][n][d]
__device__ float g_k  [2*BB*HH*NN*HD];
__device__ float g_v  [2*BB*HH*NN*HD];
__device__ float g_ctx[2*BB*HH*NN*HD];   // [p][b][h][n][d]

// -------- tf32 helpers --------
__device__ __forceinline__ unsigned f2t(float x) {
    unsigned u; asm("cvt.rna.tf32.f32 %0, %1;" : "=r"(u) : "f"(x)); return u;
}
__device__ __forceinline__ void mma8(float* c, const unsigned* a, const unsigned* b) {
    asm volatile("mma.sync.aligned.m16n8k8.row.col.f32.tf32.tf32.f32 "
        "{%0,%1,%2,%3}, {%4,%5,%6,%7}, {%8,%9}, {%0,%1,%2,%3};"
        : "+f"(c[0]), "+f"(c[1]), "+f"(c[2]), "+f"(c[3])
        : "r"(a[0]), "r"(a[1]), "r"(a[2]), "r"(a[3]), "r"(b[0]), "r"(b[1]));
}

#define AST 37    // A smem stride (k-pad): conflict-free staging, ~clean frag reads
#define BST 133   // B smem stride (n-pad): conflict-free staging, 2-way frag reads
#define CST 132

// =====================================================================
// Kernel 1: QKV GEMM (tf32 mma) + fused per-head LayerNorm epilogue.
// Block tile 64(M)x128(N), K-step 32. 256 thr = 8 warps (2m x 4n),
// warp tile 32x32 = 2 m-frags x 4 n-frags of m16n8k8.
// Epilogue: acc -> smem Cs[64][128], LN over 64-col head groups,
// scatter to g_q/g_k/g_v [s][b][h][n][d]. (g_qkv buffer eliminated.)
// =====================================================================
__global__ __launch_bounds__(256) void qkv_gemm_mma(
    const float* __restrict__ before, const float* __restrict__ after,
    const float* __restrict__ Wqkv, const float* __restrict__ ln_g,
    const float* __restrict__ ln_b)
{
    __shared__ __align__(16) unsigned smu[64*CST];   // 33792B union
    unsigned* As = smu;                // [64][AST]
    unsigned* Bs = smu + 64*AST;       // [32][BST]
    float* Cs = (float*)smu;           // [64][CST]  (aliases; used post-mainloop)
    __shared__ float s_lng[64], s_lnb[64];

    const int tid = threadIdx.x;
    if (tid < 64) { s_lng[tid] = ln_g[tid]; s_lnb[tid] = ln_b[tid]; }

    const int warp = tid >> 5, lane = tid & 31;
    const int wm = warp >> 2, wn = warp & 3;
    const int g = lane >> 2, t = lane & 3;
    const int mt = blockIdx.y;
    const int bn = blockIdx.x * 128;

    // fixed per-thread staging coordinates
    const float* arow[2]; int ar[2], ac4[2];
    #pragma unroll
    for (int i = 0; i < 2; i++) {
        int f4id = tid + i*256;
        int row = f4id >> 3, c4 = (f4id & 7) * 4;
        int gm = mt*64 + row;
        arow[i] = (gm >= 4096 ? after + (size_t)(gm-4096)*CC
                              : before + (size_t)gm*CC);
        ar[i] = row; ac4[i] = c4;
    }
    const float* brow[4]; int br[4], bc4[4];
    #pragma unroll
    for (int i = 0; i < 4; i++) {
        int f4id = tid + i*256;
        int nrow = f4id >> 3, c4 = (f4id & 7) * 4;
        brow[i] = Wqkv + (size_t)(bn + nrow)*CC;
        br[i] = nrow; bc4[i] = c4;
    }

    float acc[2][4][4] = {};
    float4 pa[2], pb[4];
    #pragma unroll
    for (int i = 0; i < 2; i++) pa[i] = *(const float4*)(arow[i] + ac4[i]);
    #pragma unroll
    for (int i = 0; i < 4; i++) pb[i] = *(const float4*)(brow[i] + bc4[i]);

    for (int k0 = 0; k0 < CC; k0 += 32) {
        #pragma unroll
        for (int i = 0; i < 2; i++) {
            unsigned* d = As + ar[i]*AST + ac4[i];
            d[0] = f2t(pa[i].x); d[1] = f2t(pa[i].y);
            d[2] = f2t(pa[i].z); d[3] = f2t(pa[i].w);
        }
        #pragma unroll
        for (int i = 0; i < 4; i++) {
            unsigned* d = Bs + bc4[i]*BST + br[i];
            d[0]     = f2t(pb[i].x); d[BST]   = f2t(pb[i].y);
            d[2*BST] = f2t(pb[i].z); d[3*BST] = f2t(pb[i].w);
        }
        __syncthreads();
        if (k0 + 32 < CC) {
            #pragma unroll
            for (int i = 0; i < 2; i++) pa[i] = *(const float4*)(arow[i] + k0+32 + ac4[i]);
            #pragma unroll
            for (int i = 0; i < 4; i++) pb[i] = *(const float4*)(brow[i] + k0+32 + bc4[i]);
        }
        #pragma unroll
        for (int ks = 0; ks < 4; ks++) {
            unsigned a[2][4], bf[4][2];
            #pragma unroll
            for (int mf = 0; mf < 2; mf++) {
                const unsigned* p = As + (wm*32 + mf*16 + g)*AST + ks*8 + t;
                a[mf][0] = p[0]; a[mf][1] = p[8*AST];
                a[mf][2] = p[4]; a[mf][3] = p[8*AST+4];
            }
            #pragma unroll
            for (int nf = 0; nf < 4; nf++) {
                const unsigned* p = Bs + (ks*8 + t)*BST + wn*32 + nf*8 + g;
                bf[nf][0] = p[0]; bf[nf][1] = p[4*BST];
            }
            #pragma unroll
            for (int mf = 0; mf < 2; mf++)
                #pragma unroll
                for (int nf = 0; nf < 4; nf++)
                    mma8(acc[mf][nf], a[mf], bf[nf]);
        }
        __syncthreads();
    }

    // acc -> Cs (As/Bs are dead; aliasing is safe after the sync above)
    #pragma unroll
    for (int mf = 0; mf < 2; mf++)
        #pragma unroll
        for (int nf = 0; nf < 4; nf++) {
            int row = wm*32 + mf*16 + g, col = wn*32 + nf*8 + 2*t;
            Cs[row*CST + col]       = acc[mf][nf][0];
            Cs[row*CST + col + 1]   = acc[mf][nf][1];
            Cs[(row+8)*CST + col]   = acc[mf][nf][2];
            Cs[(row+8)*CST + col+1] = acc[mf][nf][3];
        }
    __syncthreads();

    // fused LayerNorm over head_dim=64 groups (2 groups per 128-col tile)
    if (tid < 128) {
        int row = tid >> 1, grp = tid & 1;
        const float* src = Cs + row*CST + grp*64;
        float sum = 0.f, sq = 0.f;
        #pragma unroll
        for (int j = 0; j < 64; j++) { float x = src[j]; sum += x; sq += x*x; }
        float mu = sum * (1.f/64.f);
        float var = sq * (1.f/64.f) - mu*mu;
        float rs = rsqrtf(var + 1e-5f);
        int gm = mt*64 + row;
        int s = gm >> 12, b = (gm >> 10) & 3, n = gm & 1023;
        int tq = bn / CC;                     // 0=q,1=k,2=v (128 | 768, no straddle)
        int h = ((bn % CC) >> 6) + grp;
        float* dst = (tq == 0 ? g_q : tq == 1 ? g_k : g_v)
                   + ((((size_t)(s*BB+b)*HH + h)*NN + n)*HD);
        #pragma unroll
        for (int j = 0; j < 64; j += 4) {
            float4 o;
            o.x = (src[j+0]-mu)*rs*s_lng[j+0] + s_lnb[j+0];
            o.y = (src[j+1]-mu)*rs*s_lng[j+1] + s_lnb[j+1];
            o.z = (src[j+2]-mu)*rs*s_lng[j+2] + s_lnb[j+2];
            o.w = (src[j+3]-mu)*rs*s_lng[j+3] + s_lnb[j+3];
            *(float4*)(dst + j) = o;
        }
    }
}

// =====================================================================
// Kernel 2: attention (tf32 mma, flash-style). 128 thr = 4 warps.
// Warp w owns q-rows [w*16, w*16+16) -> softmax is fully warp-local.
// S: A=Q(16xd), B=K^T via Ks[kk][d]. PV: P re-fragmented through
// warp-private smem patch; B=V natural [kk][d].
// =====================================================================
#define QST 68   // Qs/Ks stride: frag reads hit all 32 banks (4g+t)
#define VST 72   // Vs stride: PV B-frag reads hit all 32 banks (8t+g)
#define PST 68

__global__ __launch_bounds__(128) void attn_mma() {
    extern __shared__ unsigned sm[];
    unsigned* Qs = sm;                     // [64][QST]
    unsigned* Ks = Qs + 64*QST;            // [64][QST]
    unsigned* Vs = Ks + 64*QST;            // [64][VST]
    unsigned* Ps = Vs + 64*VST;            // [4][16][PST]

    const int bx = blockIdx.x;
    const int qt = bx & 15;
    const int h  = (bx >> 4) % 12;
    const int b  = (bx / (16*12)) & 3;
    const int p  = bx / (16*12*4);
    const int qs = 1 - p, kvs = p;

    const float* qptr = g_q + (((size_t)(qs*BB+b)*HH + h)*NN + qt*64)*HD;
    const float* kptr = g_k + (((size_t)(kvs*BB+b)*HH + h)*NN)*HD;
    const float* vptr = g_v + (((size_t)(kvs*BB+b)*HH + h)*NN)*HD;

    const int tid = threadIdx.x, w = tid >> 5, lane = tid & 31;
    const int g = lane >> 2, t = lane & 3;

    // stage Q (once)
    #pragma unroll
    for (int i = 0; i < 8; i++) {
        int f4id = tid + i*128;
        int row = f4id >> 4, c4 = (f4id & 15) * 4;
        float4 q4 = *(const float4*)(qptr + row*64 + c4);
        unsigned* d = Qs + row*QST + c4;
        d[0] = f2t(q4.x); d[1] = f2t(q4.y); d[2] = f2t(q4.z); d[3] = f2t(q4.w);
    }

    float o[8][4] = {};
    float m0 = -1e30f, m1 = -1e30f, l0 = 0.f, l1 = 0.f;
    unsigned* Pw = Ps + w*16*PST;

    for (int kc = 0; kc < 16; kc++) {
        __syncthreads();                 // prev-iter K/V/P reads done (also fences Q)
        const float* kp = kptr + kc*64*64;
        const float* vp = vptr + kc*64*64;
        #pragma unroll
        for (int i = 0; i < 8; i++) {
            int f4id = tid + i*128;
            int row = f4id >> 4, c4 = (f4id & 15) * 4;
            float4 k4 = *(const float4*)(kp + row*64 + c4);
            unsigned* dk = Ks + row*QST + c4;
            dk[0] = f2t(k4.x); dk[1] = f2t(k4.y); dk[2] = f2t(k4.z); dk[3] = f2t(k4.w);
            float4 v4 = *(const float4*)(vp + row*64 + c4);
            unsigned* dv = Vs + row*VST + c4;
            dv[0] = f2t(v4.x); dv[1] = f2t(v4.y); dv[2] = f2t(v4.z); dv[3] = f2t(v4.w);
        }
        __syncthreads();

        // S = Q K^T  (16 q-rows x 64 k-cols per warp)
        float s[8][4] = {};
        #pragma unroll
        for (int ks = 0; ks < 8; ks++) {
            unsigned a[4];
            const unsigned* ap = Qs + (w*16 + g)*QST + ks*8 + t;
            a[0] = ap[0]; a[1] = ap[8*QST]; a[2] = ap[4]; a[3] = ap[8*QST+4];
            #pragma unroll
            for (int nf = 0; nf < 8; nf++) {
                unsigned bf[2];
                const unsigned* bp = Ks + (nf*8 + g)*QST + ks*8 + t;
                bf[0] = bp[0]; bf[1] = bp[4];
                mma8(s[nf], a, bf);
            }
        }

        // online softmax (warp-local; rows g and g+8 per thread)
        float mx0 = -1e30f, mx1 = -1e30f;
        #pragma unroll
        for (int nf = 0; nf < 8; nf++) {
            #pragma unroll
            for (int j = 0; j < 4; j++) s[nf][j] *= 0.125f;
            mx0 = fmaxf(mx0, fmaxf(s[nf][0], s[nf][1]));
            mx1 = fmaxf(mx1, fmaxf(s[nf][2], s[nf][3]));
        }
        mx0 = fmaxf(mx0, __shfl_xor_sync(0xffffffffu, mx0, 1));
        mx0 = fmaxf(mx0, __shfl_xor_sync(0xffffffffu, mx0, 2));
        mx1 = fmaxf(mx1, __shfl_xor_sync(0xffffffffu, mx1, 1));
        mx1 = fmaxf(mx1, __shfl_xor_sync(0xffffffffu, mx1, 2));
        float M0 = fmaxf(m0, mx0), M1 = fmaxf(m1, mx1);
        float c0 = __expf(m0 - M0), c1 = __expf(m1 - M1);
        float ls0 = 0.f, ls1 = 0.f;
        #pragma unroll
        for (int nf = 0; nf < 8; nf++) {
            float p00 = __expf(s[nf][0] - M0), p01 = __expf(s[nf][1] - M0);
            float p10 = __expf(s[nf][2] - M1), p11 = __expf(s[nf][3] - M1);
            ls0 += p00 + p01; ls1 += p10 + p11;
            unsigned* pp = Pw + g*PST + nf*8 + 2*t;
            pp[0] = f2t(p00); pp[1] = f2t(p01);
            pp[8*PST] = f2t(p10); pp[8*PST+1] = f2t(p11);
        }
        ls0 += __shfl_xor_sync(0xffffffffu, ls0, 1);
        ls0 += __shfl_xor_sync(0xffffffffu, ls0, 2);
        ls1 += __shfl_xor_sync(0xffffffffu, ls1, 1);
        ls1 += __shfl_xor_sync(0xffffffffu, ls1, 2);
        l0 = l0*c0 + ls0; l1 = l1*c1 + ls1;
        m0 = M0; m1 = M1;
        #pragma unroll
        for (int nf = 0; nf < 8; nf++) {
            o[nf][0] *= c0; o[nf][1] *= c0; o[nf][2] *= c1; o[nf][3] *= c1;
        }
        __syncwarp();   // P visible to all lanes of this warp

        // O += P @ V
        #pragma unroll
        for (int kc2 = 0; kc2 < 8; kc2++) {
            unsigned a[4];
            const unsigned* ap = Pw + g*PST + kc2*8 + t;
            a[0] = ap[0]; a[1] = ap[8*PST]; a[2] = ap[4]; a[3] = ap[8*PST+4];
            #pragma unroll
            for (int nf = 0; nf < 8; nf++) {
                unsigned bf[2];
                const unsigned* bp = Vs + (kc2*8 + t)*VST + nf*8 + g;
                bf[0] = bp[0]; bf[1] = bp[4*VST];
                mma8(o[nf], a, bf);
            }
        }
    }

    const int qrow = qt*64 + w*16;
    float inv0 = 1.f / l0, inv1 = 1.f / l1;
    float* op = g_ctx + (((size_t)(p*BB+b)*HH + h)*NN + qrow)*HD;
    #pragma unroll
    for (int nf = 0; nf < 8; nf++) {
        *(float2*)(op + g*64 + nf*8 + 2*t)     = make_float2(o[nf][0]*inv0, o[nf][1]*inv0);
        *(float2*)(op + (g+8)*64 + nf*8 + 2*t) = make_float2(o[nf][2]*inv1, o[nf][3]*inv1);
    }
}

// =====================================================================
// Kernel 3: projection GEMM (tf32 mma) + bias + flat-q residual -> d_out.
// Same tiling as qkv; A gathered from g_ctx [p][b][h][n][d].
// =====================================================================
__global__ __launch_bounds__(256) void proj_gemm_mma(
    const float* __restrict__ Wp, const float* __restrict__ bias,
    float* __restrict__ out)
{
    __shared__ unsigned As[64*AST];
    __shared__ unsigned Bs[32*BST];

    const int tid = threadIdx.x;
    const int warp = tid >> 5, lane = tid & 31;
    const int wm = warp >> 2, wn = warp & 3;
    const int g = lane >> 2, t = lane & 3;
    const int mt = blockIdx.y;
    const int bn = blockIdx.x * 128;

    const float* abase[2]; int ar[2], ac4[2];
    #pragma unroll
    for (int i = 0; i < 2; i++) {
        int f4id = tid + i*256;
        int row = f4id >> 3, c4 = (f4id & 7) * 4;
        int gm = mt*64 + row;
        int pp = gm >> 12, bb2 = (gm >> 10) & 3, n = gm & 1023;
        abase[i] = g_ctx + (size_t)(pp*BB + bb2)*PERSB + (size_t)n*HD;
        ar[i] = row; ac4[i] = c4;
    }
    const float* brow[4]; int br[4], bc4[4];
    #pragma unroll
    for (int i = 0; i < 4; i++) {
        int f4id = tid + i*256;
        int nrow = f4id >> 3, c4 = (f4id & 7) * 4;
        brow[i] = Wp + (size_t)(bn + nrow)*CC;
        br[i] = nrow; bc4[i] = c4;
    }

    float acc[2][4][4] = {};
    float4 pa[2], pb[4];
    #pragma unroll
    for (int i = 0; i < 2; i++) {
        int k = ac4[i];
        pa[i] = *(const float4*)(abase[i] + (k >> 6)*(NN*HD) + (k & 63));
    }
    #pragma unroll
    for (int i = 0; i < 4; i++) pb[i] = *(const float4*)(brow[i] + bc4[i]);

    for (int k0 = 0; k0 < CC; k0 += 32) {
        #pragma unroll
        for (int i = 0; i < 2; i++) {
            unsigned* d = As + ar[i]*AST + ac4[i];
            d[0] = f2t(pa[i].x); d[1] = f2t(pa[i].y);
            d[2] = f2t(pa[i].z); d[3] = f2t(pa[i].w);
        }
        #pragma unroll
        for (int i = 0; i < 4; i++) {
            unsigned* d = Bs + bc4[i]*BST + br[i];
            d[0]     = f2t(pb[i].x); d[BST]   = f2t(pb[i].y);
            d[2*BST] = f2t(pb[i].z); d[3*BST] = f2t(pb[i].w);
        }
        __syncthreads();
        if (k0 + 32 < CC) {
            #pragma unroll
            for (int i = 0; i < 2; i++) {
                int k = k0 + 32 + ac4[i];
                pa[i] = *(const float4*)(abase[i] + (k >> 6)*(NN*HD) + (k & 63));
            }
            #pragma unroll
            for (int i = 0; i < 4; i++) pb[i] = *(const float4*)(brow[i] + k0+32 + bc4[i]);
        }
        #pragma unroll
        for (int ks = 0; ks < 4; ks++) {
            unsigned a[2][4], bf[4][2];
            #pragma unroll
            for (int mf = 0; mf < 2; mf++) {
                const unsigned* p = As + (wm*32 + mf*16 + g)*AST + ks*8 + t;
                a[mf][0] = p[0]; a[mf][1] = p[8*AST];
                a[mf][2] = p[4]; a[mf][3] = p[8*AST+4];
            }
            #pragma unroll
            for (int nf = 0; nf < 4; nf++) {
                const unsigned* p = Bs + (ks*8 + t)*BST + wn*32 + nf*8 + g;
                bf[nf][0] = p[0]; bf[nf][1] = p[4*BST];
            }
            #pragma unroll
            for (int mf = 0; mf < 2; mf++)
                #pragma unroll
                for (int nf = 0; nf < 4; nf++)
                    mma8(acc[mf][nf], a[mf], bf[nf]);
        }
        __syncthreads();
    }

    // epilogue: bias + flat-q residual, write d_out
    #pragma unroll
    for (int mf = 0; mf < 2; mf++) {
        int row = mt*64 + wm*32 + mf*16 + g;
        #pragma unroll
        for (int rr = 0; rr < 2; rr++) {
            int gm = row + rr*8;
            int pp = gm >> 12, bb2 = (gm >> 10) & 3, n = gm & 1023;
            const float* qres = g_q + (size_t)((1-pp)*BB + bb2)*PERSB + (size_t)n*CC;
            #pragma unroll
            for (int nf = 0; nf < 4; nf++) {
                int col = bn + wn*32 + nf*8 + 2*t;
                float2 r;
                r.x = acc[mf][nf][2*rr+0] + __ldg(bias + col)   + __ldg(qres + col);
                r.y = acc[mf][nf][2*rr+1] + __ldg(bias + col+1) + __ldg(qres + col+1);
                *(float2*)(out + (size_t)gm*CC + col) = r;
            }
        }
    }
}

// =====================================================================
extern "C" void kernel_launch(void* const* d_in, const int* in_sizes, int n_in,
                              void* d_out, int out_size) {
    const float* before = (const float*)d_in[0];
    const float* after  = (const float*)d_in[1];
    const float* W_qkv  = (const float*)d_in[2];
    const float* ln_g   = (const float*)d_in[3];
    const float* ln_b   = (const float*)d_in[4];
    const float* W_proj = (const float*)d_in[5];
    const float* b_proj = (const float*)d_in[6];
    float* out = (float*)d_out;

    // 1) QKV GEMM + fused LN: grid (2304/128, 8192/64)
    {
        dim3 grid(QKV3/128, MROWS/64);
        qkv_gemm_mma<<<grid, 256>>>(before, after, W_qkv, ln_g, ln_b);
    }
    // 2) Attention: 2*4*12*16 = 1536 blocks, 128 thr, ~69KB dyn smem
    {
        const int smem = (64*QST + 64*QST + 64*VST + 4*16*PST) * (int)sizeof(unsigned);
        cudaFuncSetAttribute(attn_mma, cudaFuncAttributeMaxDynamicSharedMemorySize, smem);
        attn_mma<<<1536, 128, smem>>>();
    }
    // 3) Projection GEMM: grid (768/128, 8192/64)
    {
        dim3 grid(CC/128, MROWS/64);
        proj_gemm_mma<<<grid, 256>>>(W_proj, b_proj, out);
    }
}

// round 4
// speedup vs baseline: 3.6832x; 1.3620x over previous
#include <cuda_runtime.h>
#include <math.h>

#define BB 4
#define NN 1024
#define CC 768
#define HH 12
#define HD 64
#define QKV3 (3*CC)          // 2304
#define MROWS (2*BB*NN)      // 8192
#define PERSB (HH*NN*HD)     // 786432 floats per (stream,b)

// -------- scratch (device globals; no allocation) --------
__device__ float g_q  [2*BB*HH*NN*HD];   // [s][b][h][n][d]
__device__ float g_k  [2*BB*HH*NN*HD];
__device__ float g_v  [2*BB*HH*NN*HD];
__device__ float g_ctx[2*BB*HH*NN*HD];   // [p][b][h][n][d]

// -------- helpers --------
__device__ __forceinline__ unsigned f2t(float x) {
    unsigned u; asm("cvt.rna.tf32.f32 %0, %1;" : "=r"(u) : "f"(x)); return u;
}
__device__ __forceinline__ unsigned u2t(unsigned x) {
    unsigned u; asm("cvt.rna.tf32.f32 %0, %1;" : "=r"(u) : "f"(__uint_as_float(x))); return u;
}
__device__ __forceinline__ void mma8(float* c, const unsigned* a, const unsigned* b) {
    asm volatile("mma.sync.aligned.m16n8k8.row.col.f32.tf32.tf32.f32 "
        "{%0,%1,%2,%3}, {%4,%5,%6,%7}, {%8,%9}, {%0,%1,%2,%3};"
        : "+f"(c[0]), "+f"(c[1]), "+f"(c[2]), "+f"(c[3])
        : "r"(a[0]), "r"(a[1]), "r"(a[2]), "r"(a[3]), "r"(b[0]), "r"(b[1]));
}
__device__ __forceinline__ void ldsm4(unsigned& r0, unsigned& r1, unsigned& r2,
                                      unsigned& r3, unsigned addr) {
    asm volatile("ldmatrix.sync.aligned.m8n8.x4.shared.b16 {%0,%1,%2,%3}, [%4];"
        : "=r"(r0), "=r"(r1), "=r"(r2), "=r"(r3) : "r"(addr));
}
__device__ __forceinline__ unsigned s2u(const void* p) {
    return (unsigned)__cvta_generic_to_shared(p);
}
__device__ __forceinline__ void cp16(unsigned dst, const float* src) {
    asm volatile("cp.async.cg.shared.global [%0], [%1], 16;" :: "r"(dst), "l"(src));
}
#define CPCOMMIT() asm volatile("cp.async.commit_group;")

// GEMM tiling constants (qkv & proj): 128x128 block, K-step 32, 8 warps (2x4)
#define KST 36               // smem row stride (words): 9x16B units, LDSM conflict-free
#define ABUFW (128*KST)      // 4608 words per A tile
#define BUFW  (2*ABUFW)      // 9216 words per stage (A + B)
#define CST 133              // epilogue C stride

// per-thread ldmatrix byte offsets (within a tile, stride KST)
#define AOFF_G(lane) ((((lane)&15)*KST + ((lane)>>4)*4)*4)
#define BOFF_G(lane) (((((((lane)>>4)<<3)) + ((lane)&7))*KST + (((lane)>>3)&1)*4)*4)

// =====================================================================
// Kernel 1: QKV GEMM (tf32 mma + ldmatrix + cp.async db) + fused LN.
// =====================================================================
__global__ __launch_bounds__(256) void qkv_gemm_mma(
    const float* __restrict__ before, const float* __restrict__ after,
    const float* __restrict__ Wqkv, const float* __restrict__ ln_g,
    const float* __restrict__ ln_b)
{
    extern __shared__ __align__(16) unsigned sq[];   // 2*BUFW words = 73728 B
    __shared__ float s_lng[64], s_lnb[64];
    const int tid = threadIdx.x;
    if (tid < 64) { s_lng[tid] = ln_g[tid]; s_lnb[tid] = ln_b[tid]; }

    const int warp = tid >> 5, lane = tid & 31;
    const int wm = warp >> 2, wn = warp & 3;
    const int g = lane >> 2, t = lane & 3;
    const int mt = blockIdx.y;
    const int bn = blockIdx.x * 128;
    const unsigned smb = s2u(sq);

    // staging slots: 1024 16B-chunks per tile pair, 4 A + 4 B per thread
    const float* asrc[4]; unsigned adst[4];
    const float* bsrc[4]; unsigned bdst[4];
    #pragma unroll
    for (int i = 0; i < 4; i++) {
        int c = tid + i*256, row = c >> 3, u4 = (c & 7) * 4;
        int gm = mt*128 + row;
        asrc[i] = (gm >= 4096 ? after + (size_t)(gm-4096)*CC
                              : before + (size_t)gm*CC) + u4;
        adst[i] = smb + (row*KST + u4)*4;
        bsrc[i] = Wqkv + (size_t)(bn + row)*CC + u4;
        bdst[i] = smb + (ABUFW + row*KST + u4)*4;
    }
    const unsigned aoff = AOFF_G(lane);
    const unsigned boff = BOFF_G(lane);

    float acc[4][4][4] = {};

    #pragma unroll
    for (int i = 0; i < 4; i++) { cp16(adst[i], asrc[i]); cp16(bdst[i], bsrc[i]); }
    CPCOMMIT();

    for (int kt = 0; kt < 24; kt++) {
        if (kt < 23) {
            unsigned bo = ((kt+1) & 1) * BUFW * 4;
            #pragma unroll
            for (int i = 0; i < 4; i++) {
                cp16(adst[i] + bo, asrc[i] + (kt+1)*32);
                cp16(bdst[i] + bo, bsrc[i] + (kt+1)*32);
            }
            CPCOMMIT();
            asm volatile("cp.async.wait_group 1;");
        } else {
            asm volatile("cp.async.wait_group 0;");
        }
        __syncthreads();
        const unsigned Ab = smb + (kt & 1) * BUFW * 4;
        const unsigned Bb = Ab + ABUFW * 4;
        #pragma unroll
        for (int ks = 0; ks < 4; ks++) {
            unsigned a[4][4], bq[4][2];
            #pragma unroll
            for (int mf = 0; mf < 4; mf++) {
                unsigned r0, r1, r2, r3;
                ldsm4(r0, r1, r2, r3, Ab + ((wm*64 + mf*16)*KST + ks*8)*4 + aoff);
                a[mf][0] = u2t(r0); a[mf][1] = u2t(r1);
                a[mf][2] = u2t(r2); a[mf][3] = u2t(r3);
            }
            #pragma unroll
            for (int j = 0; j < 2; j++) {
                unsigned r0, r1, r2, r3;
                ldsm4(r0, r1, r2, r3, Bb + ((wn*32 + j*16)*KST + ks*8)*4 + boff);
                bq[2*j][0]   = u2t(r0); bq[2*j][1]   = u2t(r1);
                bq[2*j+1][0] = u2t(r2); bq[2*j+1][1] = u2t(r3);
            }
            #pragma unroll
            for (int mf = 0; mf < 4; mf++)
                #pragma unroll
                for (int nf = 0; nf < 4; nf++)
                    mma8(acc[mf][nf], a[mf], bq[nf]);
        }
        __syncthreads();
    }

    // epilogue: acc -> Cs (reuses buffers; all compute synced), then LN
    float* Cs = (float*)sq;
    #pragma unroll
    for (int mf = 0; mf < 4; mf++)
        #pragma unroll
        for (int nf = 0; nf < 4; nf++) {
            int row = wm*64 + mf*16 + g, col = wn*32 + nf*8 + 2*t;
            Cs[row*CST + col]       = acc[mf][nf][0];
            Cs[row*CST + col + 1]   = acc[mf][nf][1];
            Cs[(row+8)*CST + col]   = acc[mf][nf][2];
            Cs[(row+8)*CST + col+1] = acc[mf][nf][3];
        }
    __syncthreads();

    {   // LayerNorm: 256 threads = 128 rows x 2 head-groups
        int row = tid >> 1, grp = tid & 1;
        const float* src = Cs + row*CST + grp*64;
        float sum = 0.f, sqs = 0.f;
        #pragma unroll
        for (int j = 0; j < 64; j++) { float x = src[j]; sum += x; sqs += x*x; }
        float mu = sum * (1.f/64.f);
        float var = sqs * (1.f/64.f) - mu*mu;
        float rs = rsqrtf(var + 1e-5f);
        int gm = mt*128 + row;
        int s = gm >> 12, b = (gm >> 10) & 3, n = gm & 1023;
        int tq = bn / CC;                       // 0=q,1=k,2=v (no straddle)
        int h = ((bn % CC) >> 6) + grp;
        float* dst = (tq == 0 ? g_q : tq == 1 ? g_k : g_v)
                   + ((((size_t)(s*BB+b)*HH + h)*NN + n)*HD);
        #pragma unroll
        for (int j = 0; j < 64; j += 4) {
            float4 o;
            o.x = (src[j+0]-mu)*rs*s_lng[j+0] + s_lnb[j+0];
            o.y = (src[j+1]-mu)*rs*s_lng[j+1] + s_lnb[j+1];
            o.z = (src[j+2]-mu)*rs*s_lng[j+2] + s_lnb[j+2];
            o.w = (src[j+3]-mu)*rs*s_lng[j+3] + s_lnb[j+3];
            *(float4*)(dst + j) = o;
        }
    }
}

// =====================================================================
// Kernel 2: attention (tf32 mma + ldmatrix). 256 thr = 8 warps,
// q-tile 128 (warp w owns rows w*16..+15 -> warp-local softmax).
// V staged transposed (Vt[d][kv]) so PV B-operand ldmatrix-loads.
// =====================================================================
#define TST 68   // 17x16B units, LDSM conflict-free

__global__ __launch_bounds__(256) void attn_mma() {
    extern __shared__ __align__(16) unsigned sa[];
    const unsigned QW = 0;
    const unsigned KW = 128*TST;
    const unsigned VW = KW + 64*TST;
    const unsigned PW = VW + 64*TST;

    const int bx = blockIdx.x;
    const int qt = bx & 7;
    const int h  = (bx >> 3) % 12;
    const int b  = (bx / 96) & 3;
    const int p  = bx / 384;
    const int qs = 1 - p, kvs = p;

    const float* qptr = g_q + (((size_t)(qs*BB+b)*HH + h)*NN + qt*128)*HD;
    const float* kptr = g_k + (((size_t)(kvs*BB+b)*HH + h)*NN)*HD;
    const float* vptr = g_v + (((size_t)(kvs*BB+b)*HH + h)*NN)*HD;

    const int tid = threadIdx.x, w = tid >> 5, lane = tid & 31;
    const int g = lane >> 2, t = lane & 3;
    const unsigned smb = s2u(sa);

    // stage Q tile (128x64), raw fp32 (cvt after ldmatrix)
    #pragma unroll
    for (int i = 0; i < 8; i++) {
        int id = tid + i*256, row = id >> 4, u4 = (id & 15)*4;
        *(float4*)&sa[QW + row*TST + u4] = *(const float4*)(qptr + row*64 + u4);
    }

    const unsigned aoff = ((( lane & 15)*TST + (lane >> 4)*4))*4;
    const unsigned boff = ((((((lane >> 4) << 3)) + (lane & 7))*TST + ((lane >> 3) & 1)*4))*4;
    const unsigned Pwb = smb + (PW + w*16*TST)*4;
    const unsigned Pwidx = PW + w*16*TST;

    float o[8][4] = {};
    float m0 = -1e30f, m1 = -1e30f, l0 = 0.f, l1 = 0.f;

    for (int kc = 0; kc < 16; kc++) {
        __syncthreads();                     // prev-iter smem reads done
        const float* kp = kptr + kc*64*64;
        const float* vp = vptr + kc*64*64;
        #pragma unroll
        for (int i = 0; i < 4; i++) {        // K: rows [kv][d]
            int id = tid + i*256, row = id >> 4, u4 = (id & 15)*4;
            *(float4*)&sa[KW + row*TST + u4] = *(const float4*)(kp + row*64 + u4);
        }
        #pragma unroll
        for (int i = 0; i < 4; i++) {        // V transposed: Vt[d][kv]
            int id = tid + i*256, d = id & 63, kvg = (id >> 6)*4;
            float4 v4;
            v4.x = vp[(kvg+0)*64 + d]; v4.y = vp[(kvg+1)*64 + d];
            v4.z = vp[(kvg+2)*64 + d]; v4.w = vp[(kvg+3)*64 + d];
            *(float4*)&sa[VW + d*TST + kvg] = v4;
        }
        __syncthreads();

        // S = Q K^T (16 q-rows x 64 kv per warp)
        float s[8][4] = {};
        #pragma unroll
        for (int ks = 0; ks < 8; ks++) {
            unsigned a[4], r0, r1, r2, r3;
            ldsm4(r0, r1, r2, r3, smb + (QW + (w*16)*TST + ks*8)*4 + aoff);
            a[0] = u2t(r0); a[1] = u2t(r1); a[2] = u2t(r2); a[3] = u2t(r3);
            #pragma unroll
            for (int j = 0; j < 4; j++) {
                unsigned q0, q1, q2, q3;
                ldsm4(q0, q1, q2, q3, smb + (KW + (j*16)*TST + ks*8)*4 + boff);
                unsigned bf0[2] = {u2t(q0), u2t(q1)};
                unsigned bf1[2] = {u2t(q2), u2t(q3)};
                mma8(s[2*j], a, bf0);
                mma8(s[2*j+1], a, bf1);
            }
        }

        // online softmax (warp-local; rows g and g+8)
        float mx0 = -1e30f, mx1 = -1e30f;
        #pragma unroll
        for (int nf = 0; nf < 8; nf++) {
            #pragma unroll
            for (int j = 0; j < 4; j++) s[nf][j] *= 0.125f;
            mx0 = fmaxf(mx0, fmaxf(s[nf][0], s[nf][1]));
            mx1 = fmaxf(mx1, fmaxf(s[nf][2], s[nf][3]));
        }
        mx0 = fmaxf(mx0, __shfl_xor_sync(0xffffffffu, mx0, 1));
        mx0 = fmaxf(mx0, __shfl_xor_sync(0xffffffffu, mx0, 2));
        mx1 = fmaxf(mx1, __shfl_xor_sync(0xffffffffu, mx1, 1));
        mx1 = fmaxf(mx1, __shfl_xor_sync(0xffffffffu, mx1, 2));
        float M0 = fmaxf(m0, mx0), M1 = fmaxf(m1, mx1);
        float c0 = __expf(m0 - M0), c1 = __expf(m1 - M1);
        float ls0 = 0.f, ls1 = 0.f;
        #pragma unroll
        for (int nf = 0; nf < 8; nf++) {
            float p00 = __expf(s[nf][0] - M0), p01 = __expf(s[nf][1] - M0);
            float p10 = __expf(s[nf][2] - M1), p11 = __expf(s[nf][3] - M1);
            ls0 += p00 + p01; ls1 += p10 + p11;
            unsigned idx = Pwidx + g*TST + nf*8 + 2*t;
            sa[idx]           = f2t(p00); sa[idx + 1]         = f2t(p01);
            sa[idx + 8*TST]   = f2t(p10); sa[idx + 8*TST + 1] = f2t(p11);
        }
        ls0 += __shfl_xor_sync(0xffffffffu, ls0, 1);
        ls0 += __shfl_xor_sync(0xffffffffu, ls0, 2);
        ls1 += __shfl_xor_sync(0xffffffffu, ls1, 1);
        ls1 += __shfl_xor_sync(0xffffffffu, ls1, 2);
        l0 = l0*c0 + ls0; l1 = l1*c1 + ls1;
        m0 = M0; m1 = M1;
        #pragma unroll
        for (int nf = 0; nf < 8; nf++) {
            o[nf][0] *= c0; o[nf][1] *= c0; o[nf][2] *= c1; o[nf][3] *= c1;
        }
        __syncwarp();                        // P visible within warp

        // O += P @ V  (A = P already tf32; B = Vt, cvt after ldmatrix)
        #pragma unroll
        for (int ks = 0; ks < 8; ks++) {
            unsigned a[4];
            ldsm4(a[0], a[1], a[2], a[3], Pwb + (ks*8)*4 + aoff);
            #pragma unroll
            for (int j = 0; j < 4; j++) {
                unsigned q0, q1, q2, q3;
                ldsm4(q0, q1, q2, q3, smb + (VW + (j*16)*TST + ks*8)*4 + boff);
                unsigned bf0[2] = {u2t(q0), u2t(q1)};
                unsigned bf1[2] = {u2t(q2), u2t(q3)};
                mma8(o[2*j], a, bf0);
                mma8(o[2*j+1], a, bf1);
            }
        }
    }

    const int qrow = qt*128 + w*16;
    float inv0 = 1.f / l0, inv1 = 1.f / l1;
    float* op = g_ctx + (((size_t)(p*BB+b)*HH + h)*NN + qrow)*HD;
    #pragma unroll
    for (int nf = 0; nf < 8; nf++) {
        *(float2*)(op + g*64 + nf*8 + 2*t)     = make_float2(o[nf][0]*inv0, o[nf][1]*inv0);
        *(float2*)(op + (g+8)*64 + nf*8 + 2*t) = make_float2(o[nf][2]*inv1, o[nf][3]*inv1);
    }
}

// =====================================================================
// Kernel 3: projection GEMM (same engine as qkv) + bias + q-residual.
// =====================================================================
__global__ __launch_bounds__(256) void proj_gemm_mma(
    const float* __restrict__ Wp, const float* __restrict__ bias,
    float* __restrict__ out)
{
    extern __shared__ __align__(16) unsigned sp[];
    const int tid = threadIdx.x;
    const int warp = tid >> 5, lane = tid & 31;
    const int wm = warp >> 2, wn = warp & 3;
    const int g = lane >> 2, t = lane & 3;
    const int mt = blockIdx.y;
    const int bn = blockIdx.x * 128;
    const unsigned smb = s2u(sp);

    const float* abase[4]; int au[4]; unsigned adst[4];
    const float* bsrc[4]; unsigned bdst[4];
    #pragma unroll
    for (int i = 0; i < 4; i++) {
        int c = tid + i*256, row = c >> 3, u4 = (c & 7) * 4;
        int gm = mt*128 + row;
        int pp = gm >> 12, b2 = (gm >> 10) & 3, n = gm & 1023;
        abase[i] = g_ctx + (size_t)(pp*BB + b2)*PERSB + (size_t)n*HD;
        au[i] = u4;
        adst[i] = smb + (row*KST + u4)*4;
        bsrc[i] = Wp + (size_t)(bn + row)*CC + u4;
        bdst[i] = smb + (ABUFW + row*KST + u4)*4;
    }
    const unsigned aoff = AOFF_G(lane);
    const unsigned boff = BOFF_G(lane);

    float acc[4][4][4] = {};

    #pragma unroll
    for (int i = 0; i < 4; i++) {
        int k = au[i];
        cp16(adst[i], abase[i] + (k >> 6)*(NN*HD) + (k & 63));
        cp16(bdst[i], bsrc[i]);
    }
    CPCOMMIT();

    for (int kt = 0; kt < 24; kt++) {
        if (kt < 23) {
            unsigned bo = ((kt+1) & 1) * BUFW * 4;
            #pragma unroll
            for (int i = 0; i < 4; i++) {
                int k = (kt+1)*32 + au[i];
                cp16(adst[i] + bo, abase[i] + (k >> 6)*(NN*HD) + (k & 63));
                cp16(bdst[i] + bo, bsrc[i] + (kt+1)*32);
            }
            CPCOMMIT();
            asm volatile("cp.async.wait_group 1;");
        } else {
            asm volatile("cp.async.wait_group 0;");
        }
        __syncthreads();
        const unsigned Ab = smb + (kt & 1) * BUFW * 4;
        const unsigned Bb = Ab + ABUFW * 4;
        #pragma unroll
        for (int ks = 0; ks < 4; ks++) {
            unsigned a[4][4], bq[4][2];
            #pragma unroll
            for (int mf = 0; mf < 4; mf++) {
                unsigned r0, r1, r2, r3;
                ldsm4(r0, r1, r2, r3, Ab + ((wm*64 + mf*16)*KST + ks*8)*4 + aoff);
                a[mf][0] = u2t(r0); a[mf][1] = u2t(r1);
                a[mf][2] = u2t(r2); a[mf][3] = u2t(r3);
            }
            #pragma unroll
            for (int j = 0; j < 2; j++) {
                unsigned r0, r1, r2, r3;
                ldsm4(r0, r1, r2, r3, Bb + ((wn*32 + j*16)*KST + ks*8)*4 + boff);
                bq[2*j][0]   = u2t(r0); bq[2*j][1]   = u2t(r1);
                bq[2*j+1][0] = u2t(r2); bq[2*j+1][1] = u2t(r3);
            }
            #pragma unroll
            for (int mf = 0; mf < 4; mf++)
                #pragma unroll
                for (int nf = 0; nf < 4; nf++)
                    mma8(acc[mf][nf], a[mf], bq[nf]);
        }
        __syncthreads();
    }

    // epilogue: bias + flat-q residual -> d_out
    #pragma unroll
    for (int mf = 0; mf < 4; mf++) {
        #pragma unroll
        for (int rr = 0; rr < 2; rr++) {
            int gm = mt*128 + wm*64 + mf*16 + g + rr*8;
            int pp = gm >> 12, b2 = (gm >> 10) & 3, n = gm & 1023;
            const float* qres = g_q + (size_t)((1-pp)*BB + b2)*PERSB + (size_t)n*CC;
            #pragma unroll
            for (int nf = 0; nf < 4; nf++) {
                int col = bn + wn*32 + nf*8 + 2*t;
                float2 r;
                r.x = acc[mf][nf][2*rr+0] + __ldg(bias + col)   + __ldg(qres + col);
                r.y = acc[mf][nf][2*rr+1] + __ldg(bias + col+1) + __ldg(qres + col+1);
                *(float2*)(out + (size_t)gm*CC + col) = r;
            }
        }
    }
}

// =====================================================================
extern "C" void kernel_launch(void* const* d_in, const int* in_sizes, int n_in,
                              void* d_out, int out_size) {
    const float* before = (const float*)d_in[0];
    const float* after  = (const float*)d_in[1];
    const float* W_qkv  = (const float*)d_in[2];
    const float* ln_g   = (const float*)d_in[3];
    const float* ln_b   = (const float*)d_in[4];
    const float* W_proj = (const float*)d_in[5];
    const float* b_proj = (const float*)d_in[6];
    float* out = (float*)d_out;

    const int gemm_smem = 2 * BUFW * 4;                  // 73728 B
    const int attn_smem = (128*TST + 64*TST + 64*TST + 8*16*TST) * 4;  // 104448 B

    // 1) QKV GEMM + fused LN: grid (2304/128, 8192/128)
    {
        cudaFuncSetAttribute(qkv_gemm_mma, cudaFuncAttributeMaxDynamicSharedMemorySize, gemm_smem);
        dim3 grid(QKV3/128, MROWS/128);
        qkv_gemm_mma<<<grid, 256, gemm_smem>>>(before, after, W_qkv, ln_g, ln_b);
    }
    // 2) Attention: 2*4*12*8 = 768 blocks
    {
        cudaFuncSetAttribute(attn_mma, cudaFuncAttributeMaxDynamicSharedMemorySize, attn_smem);
        attn_mma<<<768, 256, attn_smem>>>();
    }
    // 3) Projection GEMM: grid (768/128, 8192/128)
    {
        cudaFuncSetAttribute(proj_gemm_mma, cudaFuncAttributeMaxDynamicSharedMemorySize, gemm_smem);
        dim3 grid(CC/128, MROWS/128);
        proj_gemm_mma<<<grid, 256, gemm_smem>>>(W_proj, b_proj, out);
    }
}